// round 3
// baseline (speedup 1.0000x reference)
#include <cuda_runtime.h>
#include <math.h>

// Cox partial likelihood via chunk-sorted suffix sums (v3):
//   8 chunks of 2048, bitonic-sorted by order-preserving uint key of T,
//   per-chunk suffix sums of exp(theta).
//   rss[i] = sum_c sfx_c[ lower_bound_c(u_i) ]   (4-ary search, ILP across chunks)
//   loss   = -mean( (theta_i - log(rss_i)) * ev_i )

#define CHUNK 2048
#define NCH   8
#define STH   512
#define EPT   (CHUNK / STH)     // 4 elements per sort thread

__device__ unsigned g_u[NCH * CHUNK];          // sorted keys
__device__ float    g_sfx[NCH * (CHUNK + 1)];  // suffix sums (+ trailing 0)

__device__ __forceinline__ unsigned key_of(float t) {
    unsigned b = __float_as_uint(t);
    return b ^ ((unsigned)((int)b >> 31) | 0x80000000u);   // never 0 for finite t
}

__global__ void __launch_bounds__(STH)
sort_kernel(const float* __restrict__ theta, const float* __restrict__ T,
            int n, float* __restrict__ out) {
    const int c = blockIdx.x;
    const int t = threadIdx.x;

    __shared__ unsigned su[CHUNK];
    __shared__ float    se[CHUNK];

#pragma unroll
    for (int r = 0; r < EPT; r++) {
        int idx = t + r * STH;
        int j   = c * CHUNK + idx;
        unsigned u = 0u;  float e = 0.0f;          // pad key 0 < any real key
        if (j < n) { u = key_of(T[j]); e = expf(theta[j]); }
        su[idx] = u;  se[idx] = e;
    }
    __syncthreads();

    // Bitonic sort ascending (pair enumeration: 1024 pairs, 2 per thread)
    for (int k = 2; k <= CHUNK; k <<= 1) {
        for (int s = k >> 1; s > 0; s >>= 1) {
#pragma unroll
            for (int q = 0; q < CHUNK / (2 * STH); q++) {
                int p = t + q * STH;                         // pair id
                int i = ((p & ~(s - 1)) << 1) | (p & (s - 1));
                int j = i | s;
                unsigned a = su[i], b = su[j];
                if ((a > b) == ((i & k) == 0)) {
                    su[i] = b;  su[j] = a;
                    float tmp = se[i]; se[i] = se[j]; se[j] = tmp;
                }
            }
            __syncthreads();
        }
    }

    // Inclusive suffix sum (reversed Hillis-Steele, snapshot-then-write)
    for (int d = 1; d < CHUNK; d <<= 1) {
        float v[EPT];
#pragma unroll
        for (int r = 0; r < EPT; r++) {
            int idx = t + r * STH;
            v[r] = (idx + d < CHUNK) ? se[idx + d] : 0.0f;
        }
        __syncthreads();
#pragma unroll
        for (int r = 0; r < EPT; r++) se[t + r * STH] += v[r];
        __syncthreads();
    }

#pragma unroll
    for (int r = 0; r < EPT; r++) {
        int idx = t + r * STH;
        g_u[c * CHUNK + idx]         = su[idx];
        g_sfx[c * (CHUNK + 1) + idx] = se[idx];
    }
    if (t == 0) {
        g_sfx[c * (CHUNK + 1) + CHUNK] = 0.0f;
        if (c == 0) out[0] = 0.0f;                 // runs before loss_kernel
    }
}

__global__ void __launch_bounds__(128)
loss_kernel(const float* __restrict__ theta, const float* __restrict__ T,
            const float* __restrict__ ev, int n, float* __restrict__ out) {
    const int i = blockIdx.x * 128 + threadIdx.x;

    float term = 0.0f;
    if (i < n) {
        const unsigned u = key_of(T[i]);
        float rss = 0.0f;
#pragma unroll
        for (int c = 0; c < NCH; c++) {            // 8 independent search chains
            const unsigned* __restrict__ A = g_u + c * CHUNK;
            int lo = 0;
#pragma unroll
            for (int m = CHUNK / 4; m >= 2; m >>= 2) {   // m = 512,128,32,8,2
                unsigned a0 = __ldg(A + lo +     m - 1); // 3 independent loads
                unsigned a1 = __ldg(A + lo + 2 * m - 1);
                unsigned a2 = __ldg(A + lo + 3 * m - 1);
                lo += m * ((a0 < u) + (a1 < u) + (a2 < u));
            }
            unsigned b0 = __ldg(A + lo), b1 = __ldg(A + lo + 1); // final len-2
            lo += (b0 < u) + (b1 < u);
            rss += __ldg(g_sfx + c * (CHUNK + 1) + lo);
        }
        term = (theta[i] - logf(rss)) * ev[i];
    }

    for (int off = 16; off > 0; off >>= 1)
        term += __shfl_down_sync(0xFFFFFFFFu, term, off);

    __shared__ float wsum[4];
    const int lane = threadIdx.x & 31, warp = threadIdx.x >> 5;
    if (lane == 0) wsum[warp] = term;
    __syncthreads();
    if (threadIdx.x == 0) {
        float s = wsum[0] + wsum[1] + wsum[2] + wsum[3];
        atomicAdd(out, -s / (float)n);
    }
}

extern "C" void kernel_launch(void* const* d_in, const int* in_sizes, int n_in,
                              void* d_out, int out_size) {
    const float* theta = (const float*)d_in[0];   // risk_scores
    const float* T     = (const float*)d_in[1];   // survival_times
    const float* ev    = (const float*)d_in[2];   // events
    float*       out   = (float*)d_out;
    const int n = in_sizes[0];                    // 16384

    sort_kernel<<<NCH, STH>>>(theta, T, n, out);
    loss_kernel<<<(n + 127) / 128, 128>>>(theta, T, ev, n, out);
}

// round 4
// speedup vs baseline: 1.7391x; 1.7391x over previous
#include <cuda_runtime.h>
#include <math.h>

// Cox partial likelihood, chunk-sorted (v4):
//   32 chunks of 512 sorted by key(T) with payload (e=exp(theta), orig idx),
//   per-chunk suffix sums of e.
//   For each SORTED slot s (tile, t): rss = sum_c sfx_c[lower_bound_c(u_s)]
//   computed with both sides sorted -> SMEM searches, near-conflict-free.
//   loss = -mean( (theta_i - log(rss_i)) * ev_i ), scattered via idx.

#define NN     16384
#define TILE   512
#define NCH    32           // NN / TILE
#define GROUPS 8
#define CPG    (NCH / GROUPS)   // 4 chunks per group

__device__ unsigned g_u  [NCH * TILE];        // sorted keys
__device__ float    g_sfx[NCH * (TILE + 1)];  // suffix sums (+0 sentinel)
__device__ int      g_idx[NCH * TILE];        // original index per sorted slot
__device__ float    g_part[GROUPS * NN];      // per-group partial rss (by slot)

__device__ __forceinline__ unsigned key_of(float t) {
    unsigned b = __float_as_uint(t);
    return b ^ ((unsigned)((int)b >> 31) | 0x80000000u);   // never 0 for finite t
}

__global__ void __launch_bounds__(TILE)
sort_kernel(const float* __restrict__ theta, const float* __restrict__ T,
            int n, float* __restrict__ out) {
    const int c = blockIdx.x;
    const int t = threadIdx.x;
    const int j = c * TILE + t;

    unsigned u = 0u;  float e = 0.0f;
    if (j < n) { u = key_of(T[j]); e = expf(theta[j]); }

    __shared__ unsigned su[TILE];
    __shared__ float    se[TILE];
    __shared__ int      si[TILE];
    su[t] = u;  se[t] = e;  si[t] = j;
    __syncthreads();

    // Bitonic sort ascending by key (payload e, idx travel along)
    for (int k = 2; k <= TILE; k <<= 1) {
        for (int s = k >> 1; s > 0; s >>= 1) {
            int ixj = t ^ s;
            if (ixj > t) {
                unsigned a = su[t], b = su[ixj];
                if ((a > b) == ((t & k) == 0)) {
                    su[t] = b;  su[ixj] = a;
                    float ea = se[t]; se[t] = se[ixj]; se[ixj] = ea;
                    int   ia = si[t]; si[t] = si[ixj]; si[ixj] = ia;
                }
            }
            __syncthreads();
        }
    }

    // Inclusive suffix sum of se
    for (int d = 1; d < TILE; d <<= 1) {
        float tmp = (t + d < TILE) ? se[t + d] : 0.0f;
        __syncthreads();
        se[t] += tmp;
        __syncthreads();
    }

    g_u  [c * TILE + t]       = su[t];
    g_sfx[c * (TILE + 1) + t] = se[t];
    g_idx[c * TILE + t]       = si[t];
    if (t == 0) {
        g_sfx[c * (TILE + 1) + TILE] = 0.0f;
        if (c == 0) out[0] = 0.0f;        // stream-ordered before loss_kernel
    }
}

// grid = NCH * GROUPS = 256 CTAs; CTA (tile, grp) ranks tile's 512 sorted keys
// against 4 chunks staged in SMEM.
__global__ void __launch_bounds__(TILE)
rank_kernel() {
    const int tile = blockIdx.x / GROUPS;
    const int grp  = blockIdx.x % GROUPS;
    const int t    = threadIdx.x;

    __shared__ unsigned ik[TILE];
    __shared__ unsigned ck[CPG][TILE];
    __shared__ float    cs[CPG][TILE + 1];

    ik[t] = g_u[tile * TILE + t];
#pragma unroll
    for (int q = 0; q < CPG; q++) {
        const int c = grp * CPG + q;
        ck[q][t] = g_u[c * TILE + t];
        cs[q][t] = g_sfx[c * (TILE + 1) + t];
        if (t == 0) cs[q][TILE] = 0.0f;
    }
    __syncthreads();

    const unsigned u = ik[t];
    int lo[CPG];
#pragma unroll
    for (int q = 0; q < CPG; q++) lo[q] = 0;

    // 4 independent 9-deep SMEM binary-search chains
#pragma unroll
    for (int s = TILE / 2; s > 0; s >>= 1) {
#pragma unroll
        for (int q = 0; q < CPG; q++)
            if (ck[q][lo[q] + s - 1] < u) lo[q] += s;
    }

    float acc = 0.0f;
#pragma unroll
    for (int q = 0; q < CPG; q++) acc += cs[q][lo[q]];

    g_part[grp * NN + tile * TILE + t] = acc;
}

__global__ void __launch_bounds__(TILE)
loss_kernel(const float* __restrict__ theta, const float* __restrict__ ev,
            int n, float* __restrict__ out) {
    const int s = blockIdx.x * TILE + threadIdx.x;   // sorted slot

    float term = 0.0f;
    if (s < n) {
        float rss = 0.0f;
#pragma unroll
        for (int g = 0; g < GROUPS; g++) rss += g_part[g * NN + s];
        const int io = g_idx[s];
        term = (theta[io] - logf(rss)) * ev[io];
    }

    for (int off = 16; off > 0; off >>= 1)
        term += __shfl_down_sync(0xFFFFFFFFu, term, off);

    __shared__ float wsum[TILE / 32];
    const int lane = threadIdx.x & 31, warp = threadIdx.x >> 5;
    if (lane == 0) wsum[warp] = term;
    __syncthreads();
    if (threadIdx.x == 0) {
        float ssum = 0.0f;
#pragma unroll
        for (int w = 0; w < TILE / 32; w++) ssum += wsum[w];
        atomicAdd(out, -ssum / (float)n);
    }
}

extern "C" void kernel_launch(void* const* d_in, const int* in_sizes, int n_in,
                              void* d_out, int out_size) {
    const float* theta = (const float*)d_in[0];   // risk_scores
    const float* T     = (const float*)d_in[1];   // survival_times
    const float* ev    = (const float*)d_in[2];   // events
    float*       out   = (float*)d_out;
    const int n = in_sizes[0];                    // 16384

    sort_kernel<<<NCH, TILE>>>(theta, T, n, out);
    rank_kernel<<<NCH * GROUPS, TILE>>>();
    loss_kernel<<<NCH, TILE>>>(theta, ev, n, out);
}

// round 5
// speedup vs baseline: 2.5553x; 1.4693x over previous
#include <cuda_runtime.h>
#include <math.h>

// Cox partial likelihood, chunk-sorted (v5):
//   32 chunks of 512 sorted by key(T) (payload e=exp(theta), orig idx) using
//   warp-shuffle bitonic (SMEM+barrier only for stride>=32), per-chunk suffix
//   sums of e via shuffle scan. rank: both-sides-sorted SMEM binary searches.
//   loss = -mean( (theta_i - log(rss_i)) * ev_i ).

#define NN     16384
#define TILE   512
#define NCH    32
#define GROUPS 8
#define CPG    (NCH / GROUPS)   // 4

__device__ unsigned g_u  [NCH * TILE];
__device__ float    g_sfx[NCH * (TILE + 1)];
__device__ int      g_idx[NCH * TILE];
__device__ float    g_part[GROUPS * NN];

__device__ __forceinline__ unsigned key_of(float t) {
    unsigned b = __float_as_uint(t);
    return b ^ ((unsigned)((int)b >> 31) | 0x80000000u);
}

__global__ void __launch_bounds__(TILE)
sort_kernel(const float* __restrict__ theta, const float* __restrict__ T,
            int n, float* __restrict__ out) {
    const int c    = blockIdx.x;
    const int t    = threadIdx.x;
    const int lane = t & 31;
    const int w    = t >> 5;
    const int j    = c * TILE + t;

    unsigned u = 0u;  float e = 0.0f;  int idx = j;
    if (j < n) { u = key_of(T[j]); e = expf(theta[j]); }

    __shared__ unsigned su[TILE];
    __shared__ float    se[TILE];
    __shared__ int      si[TILE];
    __shared__ float    swarp[TILE / 32];
    __shared__ float    soff[TILE / 32];

    // Bitonic sort ascending by key
    for (int k = 2; k <= TILE; k <<= 1) {
        for (int s = k >> 1; s > 0; s >>= 1) {
            const bool keep_min = (((t & s) == 0) == ((t & k) == 0));
            unsigned pu;  float pe;  int pi;
            if (s >= 32) {
                su[t] = u;  se[t] = e;  si[t] = idx;
                __syncthreads();
                const int p = t ^ s;
                pu = su[p];  pe = se[p];  pi = si[p];
                __syncthreads();
            } else {
                pu = __shfl_xor_sync(0xFFFFFFFFu, u,   s);
                pe = __shfl_xor_sync(0xFFFFFFFFu, e,   s);
                pi = __shfl_xor_sync(0xFFFFFFFFu, idx, s);
            }
            const bool take = keep_min ? (pu < u) : (pu > u);
            if (take) { u = pu;  e = pe;  idx = pi; }
        }
    }

    // Inclusive suffix sum of e over sorted positions.
    float ssum = e;
#pragma unroll
    for (int off = 1; off < 32; off <<= 1) {
        float v = __shfl_down_sync(0xFFFFFFFFu, ssum, off);
        if (lane + off < 32) ssum += v;
    }
    if (lane == 0) swarp[w] = ssum;        // warp totals
    __syncthreads();
    if (t < TILE / 32) {                   // 16 lanes: exclusive suffix of totals
        float v = swarp[t];
#pragma unroll
        for (int off = 1; off < TILE / 32; off <<= 1) {
            float x = __shfl_down_sync(0xFFFFu, v, off);
            if (t + off < TILE / 32) v += x;
        }
        soff[t] = v - swarp[t];            // sum of strictly-higher warps
    }
    __syncthreads();
    const float sfx = ssum + soff[w];

    g_u  [c * TILE + t]       = u;
    g_sfx[c * (TILE + 1) + t] = sfx;
    g_idx[c * TILE + t]       = idx;
    if (t == 0) {
        g_sfx[c * (TILE + 1) + TILE] = 0.0f;
        if (c == 0) out[0] = 0.0f;
    }
}

__global__ void __launch_bounds__(TILE)
rank_kernel() {
    const int tile = blockIdx.x / GROUPS;
    const int grp  = blockIdx.x % GROUPS;
    const int t    = threadIdx.x;

    __shared__ unsigned ik[TILE];
    __shared__ unsigned ck[CPG][TILE];
    __shared__ float    cs[CPG][TILE + 1];

    ik[t] = g_u[tile * TILE + t];
#pragma unroll
    for (int q = 0; q < CPG; q++) {
        const int c = grp * CPG + q;
        ck[q][t] = g_u[c * TILE + t];
        cs[q][t] = g_sfx[c * (TILE + 1) + t];
        if (t == 0) cs[q][TILE] = 0.0f;
    }
    __syncthreads();

    const unsigned u = ik[t];
    int lo[CPG];
#pragma unroll
    for (int q = 0; q < CPG; q++) lo[q] = 0;
#pragma unroll
    for (int s = TILE / 2; s > 0; s >>= 1) {
#pragma unroll
        for (int q = 0; q < CPG; q++)
            if (ck[q][lo[q] + s - 1] < u) lo[q] += s;
    }

    float acc = 0.0f;
#pragma unroll
    for (int q = 0; q < CPG; q++) acc += cs[q][lo[q]];

    g_part[grp * NN + tile * TILE + t] = acc;
}

__global__ void __launch_bounds__(TILE)
loss_kernel(const float* __restrict__ theta, const float* __restrict__ ev,
            int n, float* __restrict__ out) {
    const int s = blockIdx.x * TILE + threadIdx.x;

    float term = 0.0f;
    if (s < n) {
        float rss = 0.0f;
#pragma unroll
        for (int g = 0; g < GROUPS; g++) rss += g_part[g * NN + s];
        const int io = g_idx[s];
        term = (theta[io] - logf(rss)) * ev[io];
    }

    for (int off = 16; off > 0; off >>= 1)
        term += __shfl_down_sync(0xFFFFFFFFu, term, off);

    __shared__ float wsum[TILE / 32];
    const int lane = threadIdx.x & 31, warp = threadIdx.x >> 5;
    if (lane == 0) wsum[warp] = term;
    __syncthreads();
    if (threadIdx.x == 0) {
        float ssum = 0.0f;
#pragma unroll
        for (int w = 0; w < TILE / 32; w++) ssum += wsum[w];
        atomicAdd(out, -ssum / (float)n);
    }
}

extern "C" void kernel_launch(void* const* d_in, const int* in_sizes, int n_in,
                              void* d_out, int out_size) {
    const float* theta = (const float*)d_in[0];
    const float* T     = (const float*)d_in[1];
    const float* ev    = (const float*)d_in[2];
    float*       out   = (float*)d_out;
    const int n = in_sizes[0];

    sort_kernel<<<NCH, TILE>>>(theta, T, n, out);
    rank_kernel<<<NCH * GROUPS, TILE>>>();
    loss_kernel<<<NCH, TILE>>>(theta, ev, n, out);
}